// round 1
// baseline (speedup 1.0000x reference)
#include <cuda_runtime.h>
#include <math.h>

// Problem constants
// B=8, CI=CO=64, H=W=256, M1=M2=16, G=4, NEXP=15, RANK=4, SCALING=0.1
// x_ft needed only at kx in [0,64)u[192,256) (128 rows, "kxIdx") and ky in [0,64).
#define NTOT (8*64*256*256)   // 33554432 floats of y

// ---------------- scratch (device globals; no allocation allowed) ----------------
__device__ float  d_FW [256*128];       // forward W-DFT matrix  [w][2*ky + re/im]
__device__ float2 d_FH [128*256];       // forward H-DFT matrix  [kxIdx][h]
__device__ float2 d_FHI[256*128];       // inverse H matrix      [h][kxIdx]
__device__ float  d_FIW[128*256];       // inverse W matrix      [2*ky+c][w]  (1/(H*W) folded)
__device__ float  d_A  [512*256*128];   // stage1 out: [bc][h][2*ky+c]           (67 MB)
__device__ float2 d_Xf [512*128*64];    // x_ft corners [bc][kxIdx][ky]          (33 MB)
__device__ float2 d_Of [512*128*64];    // out_ft corners [bo][kxIdx][ky]        (33 MB)
__device__ float  d_Z  [512*256*128];   // stage5 out: [bo][h][2*ky+c]           (67 MB)
__device__ float2 d_wt [2*256*64*64];   // transposed base weights [t][p][i][o]  (17 MB)
__device__ float2 d_lbt[2*15*256*4*64]; // transposed lora_b [t][e][p][r][o]     (16 MB)
__device__ float2 d_la [2*15*4*64];     // lora_a complex [t][e][r][i]
__device__ float  d_gate[30];           // sigmoid(gate) [t*15+e]

__device__ __forceinline__ void cfma(float2& c, float2 a, float2 b) {
    c.x = fmaf(a.x, b.x, c.x); c.x = fmaf(-a.y, b.y, c.x);
    c.y = fmaf(a.x, b.y, c.y); c.y = fmaf( a.y, b.x, c.y);
}

// ---------------- init: trig tables (index reduced mod 256 -> exact periodicity) ----------------
__global__ void init_tables_k() {
    int id = blockIdx.x * 256 + threadIdx.x;
    const float STEP = 6.283185307179586f / 256.0f;
    if (id < 32768) {                       // FW: rfft along W, ky<64
        int w = id >> 7, n = id & 127, ky = n >> 1;
        float ang = STEP * (float)((w * ky) & 255);
        d_FW[id] = (n & 1) ? -sinf(ang) : cosf(ang);
    } else if (id < 65536) {                // FH: fft along H at selected kx
        int r = id - 32768; int kxi = r >> 8, h = r & 255;
        int kx = (kxi < 64) ? kxi : kxi + 128;     // 64..127 -> 192..255
        float ang = STEP * (float)((kx * h) & 255);
        d_FH[r] = make_float2(cosf(ang), -sinf(ang));
    } else if (id < 98304) {                // FHI: ifft along H (sum over nonzero kx only)
        int r = id - 65536; int h = r >> 7, kxi = r & 127;
        int kx = (kxi < 64) ? kxi : kxi + 128;
        float ang = STEP * (float)((kx * h) & 255);
        d_FHI[r] = make_float2(cosf(ang), sinf(ang));
    } else if (id < 131072) {               // FIW: irfft along W; scale 1/(256*256)
        int r = id - 98304; int n = r >> 8, w = r & 255, k = n >> 1;
        float s = ((k == 0) ? 1.0f : 2.0f) * (1.0f / 65536.0f);
        float ang = STEP * (float)((k * w) & 255);
        d_FIW[r] = (n & 1) ? -s * sinf(ang) : s * cosf(ang);   // sin(0)=0 handles Im(ky=0) drop
    }
}

// transpose base weights to [t][p][i][o] (o fastest -> coalesced in spectral stage)
__global__ void init_wt_k(const float* __restrict__ w1re, const float* __restrict__ w1im,
                          const float* __restrict__ w2re, const float* __restrict__ w2im) {
    int id = blockIdx.x * 256 + threadIdx.x;           // 2*256*4096
    if (id >= 2 * 256 * 4096) return;
    int t = id >> 20, rem = id & 1048575;
    int p = rem >> 12, io = rem & 4095;
    int i = io >> 6, o = io & 63;
    const float* re = t ? w2re : w1re;
    const float* im = t ? w2im : w1im;
    size_t src = ((size_t)(i * 64 + o)) * 256 + p;     // w[i][o][x][y]
    d_wt[id] = make_float2(re[src], im[src]);
}

// transpose lora_b to [t][e][p][r][o]
__global__ void init_lbt_k(const float* __restrict__ b1re, const float* __restrict__ b1im,
                           const float* __restrict__ b2re, const float* __restrict__ b2im) {
    int id = blockIdx.x * 256 + threadIdx.x;           // 2*15*256*256
    if (id >= 2 * 15 * 256 * 256) return;
    int t = id / 983040, rem = id % 983040;
    int e = rem >> 16, rem2 = rem & 65535;
    int p = rem2 >> 8, ro = rem2 & 255;
    int r = ro >> 6, o = ro & 63;
    const float* re = t ? b2re : b1re;
    const float* im = t ? b2im : b1im;
    size_t src = (((size_t)(e * 64 + o)) * 4 + r) * 256 + p;  // lb[e][o][r][x][y]
    d_lbt[id] = make_float2(re[src], im[src]);
}

__global__ void init_small_k(const float* __restrict__ la1re, const float* __restrict__ la1im,
                             const float* __restrict__ la2re, const float* __restrict__ la2im,
                             const float* __restrict__ g1, const float* __restrict__ g2,
                             float* sp_out) {
    int tid = threadIdx.x;
    for (int id = tid; id < 7680; id += 256) {
        int t = id / 3840, rem = id % 3840;            // rem = e*256 + r*64 + i  (matches la layout)
        const float* re = t ? la2re : la1re;
        const float* im = t ? la2im : la1im;
        d_la[id] = make_float2(re[rem], im[rem]);
    }
    if (tid < 30) {
        float v = (tid < 15) ? g1[tid] : g2[tid - 15];
        d_gate[tid] = 1.0f / (1.0f + expf(-v));
    }
    if (tid == 0 && sp_out) {
        float s = 0.0f;
        for (int i = 0; i < 15; i++)
            s += 1.0f / (1.0f + expf(-g1[i])) + 1.0f / (1.0f + expf(-g2[i]));
        *sp_out = s / 15.0f;
    }
}

// ---------------- generic fp32 SGEMM: C[128·gx, 128·gy..] = A[M,K] * B[K,N] ----------------
// BM=128, BN=128, BK=16, 256 threads, 8x8 micro-tile.
__global__ __launch_bounds__(256) void sgemm_k(const float* __restrict__ Amat,
                                               const float* __restrict__ Bmat,
                                               float* __restrict__ Cmat,
                                               int Kdim, int Ncols) {
    __shared__ float As[16][128];
    __shared__ float Bs[16][128];
    int tid = threadIdx.x;
    int m0 = blockIdx.x * 128, n0 = blockIdx.y * 128;
    int tx = tid & 15, ty = tid >> 4;
    float acc[8][8] = {};
    for (int k0 = 0; k0 < Kdim; k0 += 16) {
#pragma unroll
        for (int l = 0; l < 2; l++) {
            int flat = tid + l * 256;
            int row = flat >> 2, c4 = (flat & 3) * 4;
            float4 v = *(const float4*)(Amat + (size_t)(m0 + row) * Kdim + k0 + c4);
            As[c4 + 0][row] = v.x; As[c4 + 1][row] = v.y;
            As[c4 + 2][row] = v.z; As[c4 + 3][row] = v.w;
        }
#pragma unroll
        for (int l = 0; l < 2; l++) {
            int flat = tid + l * 256;
            int row = flat >> 5, c4 = (flat & 31) * 4;
            *(float4*)(&Bs[row][c4]) = *(const float4*)(Bmat + (size_t)(k0 + row) * Ncols + n0 + c4);
        }
        __syncthreads();
#pragma unroll
        for (int k = 0; k < 16; k++) {
            float a[8], b[8];
#pragma unroll
            for (int i = 0; i < 4; i++) { a[i] = As[k][ty * 4 + i]; a[4 + i] = As[k][64 + ty * 4 + i]; }
#pragma unroll
            for (int j = 0; j < 4; j++) { b[j] = Bs[k][tx * 4 + j]; b[4 + j] = Bs[k][64 + tx * 4 + j]; }
#pragma unroll
            for (int i = 0; i < 8; i++)
#pragma unroll
                for (int j = 0; j < 8; j++)
                    acc[i][j] = fmaf(a[i], b[j], acc[i][j]);
        }
        __syncthreads();
    }
#pragma unroll
    for (int i = 0; i < 8; i++) {
        int m = m0 + ((i < 4) ? (ty * 4 + i) : (64 + ty * 4 + (i - 4)));
        float4 v0 = {acc[i][0], acc[i][1], acc[i][2], acc[i][3]};
        float4 v1 = {acc[i][4], acc[i][5], acc[i][6], acc[i][7]};
        *(float4*)(Cmat + (size_t)m * Ncols + n0 + tx * 4)      = v0;
        *(float4*)(Cmat + (size_t)m * Ncols + n0 + 64 + tx * 4) = v1;
    }
}

// ---------------- batched complex GEMM: C[bat][M,64] = F[M,K] (shared) * Bm[bat][K,64] ----------
// BM=64, BN=64, BK=16, 256 threads, 4x4 complex micro-tile.
__global__ __launch_bounds__(256) void cgemm_k(const float2* __restrict__ F,
                                               const float2* __restrict__ Bm,
                                               float2* __restrict__ Cm,
                                               int Mdim, int Kdim) {
    int bat = blockIdx.x;
    int m0 = blockIdx.y * 64;
    const float2* Bb = Bm + (size_t)bat * Kdim * 64;
    float2* Cb = Cm + (size_t)bat * Mdim * 64;
    __shared__ float2 Fs[16][64];
    __shared__ float2 Bs[16][64];
    int tid = threadIdx.x;
    int tx = tid & 15, ty = tid >> 4;
    float2 acc[4][4] = {};
    for (int k0 = 0; k0 < Kdim; k0 += 16) {
#pragma unroll
        for (int l = 0; l < 2; l++) {
            int flat = tid + l * 256;
            int row = flat >> 3, c = flat & 7;
            float4 v = *(const float4*)(F + (size_t)(m0 + row) * Kdim + k0 + c * 2);
            Fs[c * 2][row]     = make_float2(v.x, v.y);
            Fs[c * 2 + 1][row] = make_float2(v.z, v.w);
        }
#pragma unroll
        for (int l = 0; l < 2; l++) {
            int flat = tid + l * 256;
            int row = flat >> 5, c = flat & 31;
            *(float4*)(&Bs[row][c * 2]) = *(const float4*)(Bb + (size_t)(k0 + row) * 64 + c * 2);
        }
        __syncthreads();
#pragma unroll
        for (int k = 0; k < 16; k++) {
            float2 f[4], b[4];
#pragma unroll
            for (int i = 0; i < 4; i++) f[i] = Fs[k][ty * 4 + i];
#pragma unroll
            for (int j = 0; j < 4; j++) b[j] = Bs[k][tx * 4 + j];
#pragma unroll
            for (int i = 0; i < 4; i++)
#pragma unroll
                for (int j = 0; j < 4; j++)
                    cfma(acc[i][j], f[i], b[j]);
        }
        __syncthreads();
    }
#pragma unroll
    for (int i = 0; i < 4; i++) {
        int m = m0 + ty * 4 + i;
#pragma unroll
        for (int j = 0; j < 4; j += 2) {
            float4 v = {acc[i][j].x, acc[i][j].y, acc[i][j + 1].x, acc[i][j + 1].y};
            *(float4*)(Cb + (size_t)m * 64 + tx * 4 + j) = v;
        }
    }
}

// ---------------- base tiles: Of[b,o,p] = sum_i Xf[b,i,p] * w[i,o,p]  (2 tiles x 256 p) --------
__global__ __launch_bounds__(512) void base_mul_k() {
    int t = blockIdx.x;                 // 0: top (0,0) w1 ; 1: bottom (3,0) w2
    int p = blockIdx.y;
    int x = p >> 4, y = p & 15;
    int kxIdx = (t == 0) ? x : (112 + x);
    int ky = y;
    __shared__ float2 Xs[8][64];
    int tid = threadIdx.x;
    {
        int b = tid >> 6, i = tid & 63;
        Xs[b][i] = d_Xf[(size_t)(b * 64 + i) * 8192 + kxIdx * 64 + ky];
    }
    __syncthreads();
    int o = tid & 63, b = tid >> 6;
    const float2* wp = d_wt + ((size_t)t * 256 + p) * 4096;   // [i][o]
    float2 s = {0.0f, 0.0f};
#pragma unroll 8
    for (int i = 0; i < 64; i++) {
        float2 w = wp[i * 64 + o];
        cfma(s, Xs[b][i], w);
    }
    d_Of[(size_t)(b * 64 + o) * 8192 + kxIdx * 64 + ky] = s;
}

// ---------------- expert tiles via LoRA factorization (30 tiles x 256 p) ----------------------
__global__ __launch_bounds__(512) void expert_mul_k() {
    int tile = blockIdx.x;              // 0..29
    int half = tile / 15, e = tile % 15;
    int p = blockIdx.y;
    int x = p >> 4, y = p & 15;
    int Rr = (e + 1) >> 2, Cc = (e + 1) & 3;
    int ky = Cc * 16 + y;
    int kxIdx = (half == 0) ? (Rr * 16 + x) : (64 + (3 - Rr) * 16 + x);
    __shared__ float2 Xs[8][64];
    __shared__ float2 Ts[8][4];
    int tid = threadIdx.x;
    {
        int b = tid >> 6, i = tid & 63;
        Xs[b][i] = d_Xf[(size_t)(b * 64 + i) * 8192 + kxIdx * 64 + ky];
    }
    __syncthreads();
    if (tid < 32) {                     // t[b][r] = sum_i Xs[b][i]*la[e][r][i]
        int b = tid >> 2, r = tid & 3;
        const float2* lap = d_la + (size_t)(half * 15 + e) * 256 + r * 64;
        float2 s = {0.0f, 0.0f};
#pragma unroll 8
        for (int i = 0; i < 64; i++) cfma(s, Xs[b][i], lap[i]);
        Ts[b][r] = s;
    }
    __syncthreads();
    int o = tid & 63, b = tid >> 6;
    const float2* lbp = d_lbt + ((size_t)(half * 15 + e) * 256 + p) * 256;  // [r][o]
    float2 s = {0.0f, 0.0f};
#pragma unroll
    for (int r = 0; r < 4; r++) {
        float2 w = lbp[r * 64 + o];
        cfma(s, Ts[b][r], w);
    }
    float g = d_gate[half * 15 + e] * 0.1f;       // gate * SCALING
    s.x *= g; s.y *= g;
    d_Of[(size_t)(b * 64 + o) * 8192 + kxIdx * 64 + ky] = s;
}

// ---------------------------------- launch ----------------------------------
extern "C" void kernel_launch(void* const* d_in, const int* in_sizes, int n_in,
                              void* d_out, int out_size) {
    const float* x     = (const float*)d_in[0];
    const float* w1re  = (const float*)d_in[1];
    const float* w1im  = (const float*)d_in[2];
    const float* w2re  = (const float*)d_in[3];
    const float* w2im  = (const float*)d_in[4];
    const float* la1re = (const float*)d_in[5];
    const float* la1im = (const float*)d_in[6];
    const float* lb1re = (const float*)d_in[7];
    const float* lb1im = (const float*)d_in[8];
    const float* la2re = (const float*)d_in[9];
    const float* la2im = (const float*)d_in[10];
    const float* lb2re = (const float*)d_in[11];
    const float* lb2im = (const float*)d_in[12];
    const float* g1    = (const float*)d_in[13];
    const float* g2    = (const float*)d_in[14];
    float* out = (float*)d_out;

    void *pA, *pZ, *pXf, *pOf, *pFW, *pFH, *pFHI, *pFIW;
    cudaGetSymbolAddress(&pA, d_A);
    cudaGetSymbolAddress(&pZ, d_Z);
    cudaGetSymbolAddress(&pXf, d_Xf);
    cudaGetSymbolAddress(&pOf, d_Of);
    cudaGetSymbolAddress(&pFW, d_FW);
    cudaGetSymbolAddress(&pFH, d_FH);
    cudaGetSymbolAddress(&pFHI, d_FHI);
    cudaGetSymbolAddress(&pFIW, d_FIW);

    float* sp_out = (out_size > NTOT) ? (out + NTOT) : nullptr;

    init_tables_k<<<512, 256>>>();
    init_wt_k<<<8192, 256>>>(w1re, w1im, w2re, w2im);
    init_lbt_k<<<7680, 256>>>(lb1re, lb1im, lb2re, lb2im);
    init_small_k<<<1, 256>>>(la1re, la1im, la2re, la2im, g1, g2, sp_out);

    // K1: A[bc*h][2ky+c] = x[bc*h][w] * FW[w][2ky+c]     (M=131072, K=256, N=128)
    sgemm_k<<<dim3(1024, 1), 256>>>(x, (const float*)pFW, (float*)pA, 256, 128);
    // K2: Xf[bc][kxIdx][ky] = FH[kxIdx][h] * A[bc][h][ky] (complex, M=128, K=256)
    cgemm_k<<<dim3(512, 2), 256>>>((const float2*)pFH, (const float2*)pA, (float2*)pXf, 128, 256);
    // spectral multiply (base tiles + 30 LoRA expert tiles; covers all 128x64 modes)
    base_mul_k<<<dim3(2, 256), 512>>>();
    expert_mul_k<<<dim3(30, 256), 512>>>();
    // K5: Z[bo][h][ky] = FHI[h][kxIdx] * Of[bo][kxIdx][ky] (complex, M=256, K=128)
    cgemm_k<<<dim3(512, 4), 256>>>((const float2*)pFHI, (const float2*)pOf, (float2*)pZ, 256, 128);
    // K6: y[bo*h][w] = Z[bo*h][2ky+c] * FIW[2ky+c][w]     (M=131072, K=128, N=256)
    sgemm_k<<<dim3(1024, 2), 256>>>((const float*)pZ, (const float*)pFIW, out, 128, 256);
}